// round 14
// baseline (speedup 1.0000x reference)
#include <cuda_runtime.h>
#include <cuda_fp16.h>
#include <cstdint>

#define HID   32
#define EDIM  16
#define EH    128
#define TE    256
#define NTH   256
#define X_STRIDE 33

// ---- smem offsets (bytes) ----
#define OFF_X    0              // 256 x 33 f32 = 33792
#define OFF_B2   33792          // 4096 -> 37888
#define OFF_W1H  37888          // 4096
#define OFF_W1L  41984          // 4096
#define OFF_B1   46080          // 512  -> 46592
#define OFF_BB   46592          // 131072 resident half-B -> 177664
#define SMEM_TOTAL 177664       // 1 CTA/SM (persistent)

// W2 fp16 fragments, k-split halves:
// [half(2)][nt(128)][kp2(2)][lane(32)] = uint4{ksA.b01,ksA.b23 ; ksB.b01,ksB.b23}
// half h covers global k rows [64h, 64h+64) i.e. global ks in [4h, 4h+4)
__device__ uint4 g_Bfrag[2 * 128 * 2 * 32];
// W1 fp16 hi/lo fragments: [nt(16)][lane(32)] = uint2
__device__ uint2 g_W1hi[16 * 32];
__device__ uint2 g_W1lo[16 * 32];

__device__ __forceinline__ uint32_t smem_u32(const void* p) {
    uint32_t a;
    asm("{ .reg .u64 t; cvta.to.shared.u64 t, %1; cvt.u32.u64 %0, t; }" : "=r"(a) : "l"(p));
    return a;
}
__device__ __forceinline__ uint32_t pkh(__half a, __half b) {
    __half2 v = __halves2half2(a, b);
    return *reinterpret_cast<uint32_t*>(&v);
}
__device__ __forceinline__ uint32_t rnd2h(float a, float b) {
    return pkh(__float2half_rn(a), __float2half_rn(b));
}
__device__ __forceinline__ void split2h(float a, float b, uint32_t& hi, uint32_t& lo) {
    __half ha = __float2half_rn(a), hb = __float2half_rn(b);
    hi = pkh(ha, hb);
    lo = pkh(__float2half_rn(a - __half2float(ha)), __float2half_rn(b - __half2float(hb)));
}
__device__ __forceinline__ void mma_f16(float& d0, float& d1, float& d2, float& d3,
                                        uint32_t a0, uint32_t a1, uint32_t a2, uint32_t a3,
                                        uint32_t b0, uint32_t b1) {
    asm volatile(
        "mma.sync.aligned.m16n8k16.row.col.f32.f16.f16.f32 "
        "{%0,%1,%2,%3}, {%4,%5,%6,%7}, {%8,%9}, {%0,%1,%2,%3};"
        : "+f"(d0), "+f"(d1), "+f"(d2), "+f"(d3)
        : "r"(a0), "r"(a1), "r"(a2), "r"(a3), "r"(b0), "r"(b1));
}

// ---------------- prep: W2 -> k-split fragment-ordered fp16 ----------------
__global__ void prep_b_kernel(const float* __restrict__ W2) {
    int idx = blockIdx.x * blockDim.x + threadIdx.x;
    if (idx >= 128 * 4 * 32) return;
    int lane = idx & 31, kp = (idx >> 5) & 3, nt = idx >> 7;
    int g = lane >> 2, c = lane & 3;
    int n = nt * 8 + g;
    uint4 r;
    {
        int k0 = (kp * 2) * 16 + 2 * c;
        r.x = rnd2h(W2[(size_t)k0 * 1024 + n], W2[(size_t)(k0 + 1) * 1024 + n]);
        r.y = rnd2h(W2[(size_t)(k0 + 8) * 1024 + n], W2[(size_t)(k0 + 9) * 1024 + n]);
        k0 = (kp * 2 + 1) * 16 + 2 * c;
        r.z = rnd2h(W2[(size_t)k0 * 1024 + n], W2[(size_t)(k0 + 1) * 1024 + n]);
        r.w = rnd2h(W2[(size_t)(k0 + 8) * 1024 + n], W2[(size_t)(k0 + 9) * 1024 + n]);
    }
    int half = kp >> 1, kp2 = kp & 1;
    g_Bfrag[half * 8192 + nt * 64 + kp2 * 32 + lane] = r;
}

// ---------------- prep: W1 -> hi/lo fragments ----------------
__global__ void prep_w1_kernel(const float* __restrict__ W1) {
    int idx = blockIdx.x * blockDim.x + threadIdx.x;
    if (idx >= 16 * 32) return;
    int lane = idx & 31, nt = idx >> 5;
    int g = lane >> 2, c = lane & 3;
    int n = nt * 8 + g;
    float v0 = W1[(2 * c) * EH + n];
    float v1 = W1[(2 * c + 1) * EH + n];
    float v2 = W1[(2 * c + 8) * EH + n];
    float v3 = W1[(2 * c + 9) * EH + n];
    uint2 hi, lo;
    split2h(v0, v1, hi.x, lo.x);
    split2h(v2, v3, hi.y, lo.y);
    g_W1hi[idx] = hi;
    g_W1lo[idx] = lo;
}

__global__ void init_out_kernel(float* __restrict__ out,
                                const float* __restrict__ bias, int n) {
    int i = blockIdx.x * blockDim.x + threadIdx.x;
    if (i < n) out[i] = bias[i & (HID - 1)];
}

// ---------------- persistent main kernel: half-B resident, k-split pairs ----------------
__global__ __launch_bounds__(NTH, 1)
void mpnn_mma_kernel(const float* __restrict__ nf,
                     const float* __restrict__ ef,
                     const int*   __restrict__ src,
                     const int*   __restrict__ dst,
                     const float* __restrict__ b1,
                     const float* __restrict__ b2,
                     float* __restrict__ out,
                     int E, int ntiles) {
    extern __shared__ __align__(1024) char sm[];
    const uint32_t sbase = smem_u32(sm);
    const int t = threadIdx.x;
    const int wid = t >> 5;
    const int lane = t & 31;
    const int half = blockIdx.x & 1;          // k rows [64*half, 64*half+64)
    const int tstep = (int)(gridDim.x >> 1);

    float* s_x   = (float*)(sm + OFF_X);
    float* s_b2  = (float*)(sm + OFF_B2);
    uint2* s_w1h = (uint2*)(sm + OFF_W1H);
    uint2* s_w1l = (uint2*)(sm + OFF_W1L);
    float* s_b1  = (float*)(sm + OFF_B1);

    // -------- prologue (once): resident half-B + W1 frags + b1 + b2 --------
    {
        const uint4* srcp = g_Bfrag + half * 8192;
#pragma unroll
        for (int j = t; j < 8192; j += NTH) {
            uint32_t d = sbase + OFF_BB + j * 16;
            size_t gp = (size_t)__cvta_generic_to_global(srcp + j);
            asm volatile("cp.async.cg.shared.global [%0], [%1], 16;"
                         :: "r"(d), "l"(gp) : "memory");
        }
        asm volatile("cp.async.commit_group;" ::: "memory");
        for (int i = t; i < 16 * 32; i += NTH) {
            s_w1h[i] = g_W1hi[i];
            s_w1l[i] = g_W1lo[i];
        }
        if (t < EH / 4) ((float4*)s_b1)[t] = ((const float4*)b1)[t];
        for (int i = t; i < HID * HID / 4; i += NTH)
            ((float4*)s_b2)[i] = ((const float4*)b2)[i];
        asm volatile("cp.async.wait_group 0;" ::: "memory");
    }
    __syncthreads();   // ONLY CTA-wide barrier in the kernel

    const int g  = lane >> 2;
    const int c4 = lane & 3;
    const int eb = wid * 32;
    const int er0 = eb + g,      er1 = er0 + 8;
    const int er2 = eb + 16 + g, er3 = er2 + 8;
    const int ob = 2 * c4;
    const uint4* bbase = (const uint4*)(sm + OFF_BB);

    for (int tile = (int)(blockIdx.x >> 1); tile < ntiles; tile += tstep) {
        const int e0g = tile * TE;

        // -------- x gather: warp-private slab --------
        {
            const float4* nfg = (const float4*)nf;
#pragma unroll
            for (int r = 0; r < 8; r++) {
                int j = r * 32 + lane;
                int el = j >> 3, c = j & 7;
                int e = eb + el, ge = e0g + e;
                float4 v = make_float4(0.f, 0.f, 0.f, 0.f);
                if (ge < E) { int sn = src[ge]; v = nfg[(size_t)sn * 8 + c]; }
                float* xr = s_x + e * X_STRIDE + c * 4;
                xr[0] = v.x; xr[1] = v.y; xr[2] = v.z; xr[3] = v.w;
            }
        }
        __syncwarp();

        // -------- phase A (this CTA's 4 ks only): h -> A frags --------
        uint32_t ehi[2][4], elo[2][4];
        {
            const int rows[2][2] = {{er0, er1}, {er2, er3}};
#pragma unroll
            for (int mt = 0; mt < 2; mt++) {
#pragma unroll
                for (int rh = 0; rh < 2; rh++) {
                    int ge = e0g + rows[mt][rh];
                    float2 p0 = make_float2(0.f, 0.f), p1 = make_float2(0.f, 0.f);
                    if (ge < E) {
                        p0 = *(const float2*)(ef + (size_t)ge * EDIM + 2 * c4);
                        p1 = *(const float2*)(ef + (size_t)ge * EDIM + 2 * c4 + 8);
                    }
                    split2h(p0.x, p0.y, ehi[mt][rh], elo[mt][rh]);
                    split2h(p1.x, p1.y, ehi[mt][2 + rh], elo[mt][2 + rh]);
                }
            }
        }

        uint32_t a0[4][4], a1[4][4];
#pragma unroll
        for (int l = 0; l < 4; l++) {
            int ks = 4 * half + l;
            uint2 whA = s_w1h[(2 * ks) * 32 + lane];
            uint2 wlA = s_w1l[(2 * ks) * 32 + lane];
            uint2 whB = s_w1h[(2 * ks + 1) * 32 + lane];
            uint2 wlB = s_w1l[(2 * ks + 1) * 32 + lane];
            float2 b1A = *(const float2*)(s_b1 + ks * 16 + 2 * c4);
            float2 b1B = *(const float2*)(s_b1 + ks * 16 + 8 + 2 * c4);
#pragma unroll
            for (int mt = 0; mt < 2; mt++) {
                float d0 = 0.f, d1 = 0.f, d2 = 0.f, d3 = 0.f;
                float f0 = 0.f, f1 = 0.f, f2 = 0.f, f3 = 0.f;
                mma_f16(d0, d1, d2, d3, ehi[mt][0], ehi[mt][1], ehi[mt][2], ehi[mt][3], whA.x, whA.y);
                mma_f16(d0, d1, d2, d3, elo[mt][0], elo[mt][1], elo[mt][2], elo[mt][3], whA.x, whA.y);
                mma_f16(d0, d1, d2, d3, ehi[mt][0], ehi[mt][1], ehi[mt][2], ehi[mt][3], wlA.x, wlA.y);
                mma_f16(f0, f1, f2, f3, ehi[mt][0], ehi[mt][1], ehi[mt][2], ehi[mt][3], whB.x, whB.y);
                mma_f16(f0, f1, f2, f3, elo[mt][0], elo[mt][1], elo[mt][2], elo[mt][3], whB.x, whB.y);
                mma_f16(f0, f1, f2, f3, ehi[mt][0], ehi[mt][1], ehi[mt][2], ehi[mt][3], wlB.x, wlB.y);
                uint32_t* A = mt ? a1[l] : a0[l];
                A[0] = rnd2h(fmaxf(d0 + b1A.x, 0.f), fmaxf(d1 + b1A.y, 0.f));
                A[1] = rnd2h(fmaxf(d2 + b1A.x, 0.f), fmaxf(d3 + b1A.y, 0.f));
                A[2] = rnd2h(fmaxf(f0 + b1B.x, 0.f), fmaxf(f1 + b1B.y, 0.f));
                A[3] = rnd2h(fmaxf(f2 + b1B.x, 0.f), fmaxf(f3 + b1B.y, 0.f));
            }
        }

        float acc[32];
#pragma unroll
        for (int i = 0; i < 32; i++) acc[i] = 0.f;

        // -------- mainloop: resident half-B, no barriers, 4 chains in flight --------
#pragma unroll 1
        for (int i = 0; i < 32; i++) {
            float xi0 = s_x[er0 * X_STRIDE + i];
            float xi1 = s_x[er1 * X_STRIDE + i];
            float xi2 = s_x[er2 * X_STRIDE + i];
            float xi3 = s_x[er3 * X_STRIDE + i];
#pragma unroll
            for (int p = 0; p < 2; p++) {
                int ntA = i * 4 + p * 2;
                const uint4* bpA = bbase + ntA * 64 + lane;
                const uint4* bpB = bpA + 64;
                float dA0 = 0.f, dA1 = 0.f, dA2 = 0.f, dA3 = 0.f;
                float fA0 = 0.f, fA1 = 0.f, fA2 = 0.f, fA3 = 0.f;
                float dB0 = 0.f, dB1 = 0.f, dB2 = 0.f, dB3 = 0.f;
                float fB0 = 0.f, fB1 = 0.f, fB2 = 0.f, fB3 = 0.f;
#pragma unroll
                for (int kp = 0; kp < 2; kp++) {
                    uint4 bA = bpA[kp * 32];
                    uint4 bB = bpB[kp * 32];
                    int l0 = kp * 2;
                    mma_f16(dA0, dA1, dA2, dA3, a0[l0][0], a0[l0][1], a0[l0][2], a0[l0][3], bA.x, bA.y);
                    mma_f16(fA0, fA1, fA2, fA3, a1[l0][0], a1[l0][1], a1[l0][2], a1[l0][3], bA.x, bA.y);
                    mma_f16(dB0, dB1, dB2, dB3, a0[l0][0], a0[l0][1], a0[l0][2], a0[l0][3], bB.x, bB.y);
                    mma_f16(fB0, fB1, fB2, fB3, a1[l0][0], a1[l0][1], a1[l0][2], a1[l0][3], bB.x, bB.y);
                    mma_f16(dA0, dA1, dA2, dA3, a0[l0 + 1][0], a0[l0 + 1][1], a0[l0 + 1][2], a0[l0 + 1][3], bA.z, bA.w);
                    mma_f16(fA0, fA1, fA2, fA3, a1[l0 + 1][0], a1[l0 + 1][1], a1[l0 + 1][2], a1[l0 + 1][3], bA.z, bA.w);
                    mma_f16(dB0, dB1, dB2, dB3, a0[l0 + 1][0], a0[l0 + 1][1], a0[l0 + 1][2], a0[l0 + 1][3], bB.z, bB.w);
                    mma_f16(fB0, fB1, fB2, fB3, a1[l0 + 1][0], a1[l0 + 1][1], a1[l0 + 1][2], a1[l0 + 1][3], bB.z, bB.w);
                }
                int qA = p * 2, qB = p * 2 + 1;
                acc[qA * 2 + 0]      = fmaf(xi0, dA0, acc[qA * 2 + 0]);
                acc[qA * 2 + 1]      = fmaf(xi0, dA1, acc[qA * 2 + 1]);
                acc[8 + qA * 2 + 0]  = fmaf(xi1, dA2, acc[8 + qA * 2 + 0]);
                acc[8 + qA * 2 + 1]  = fmaf(xi1, dA3, acc[8 + qA * 2 + 1]);
                acc[16 + qA * 2 + 0] = fmaf(xi2, fA0, acc[16 + qA * 2 + 0]);
                acc[16 + qA * 2 + 1] = fmaf(xi2, fA1, acc[16 + qA * 2 + 1]);
                acc[24 + qA * 2 + 0] = fmaf(xi3, fA2, acc[24 + qA * 2 + 0]);
                acc[24 + qA * 2 + 1] = fmaf(xi3, fA3, acc[24 + qA * 2 + 1]);
                acc[qB * 2 + 0]      = fmaf(xi0, dB0, acc[qB * 2 + 0]);
                acc[qB * 2 + 1]      = fmaf(xi0, dB1, acc[qB * 2 + 1]);
                acc[8 + qB * 2 + 0]  = fmaf(xi1, dB2, acc[8 + qB * 2 + 0]);
                acc[8 + qB * 2 + 1]  = fmaf(xi1, dB3, acc[8 + qB * 2 + 1]);
                acc[16 + qB * 2 + 0] = fmaf(xi2, fB0, acc[16 + qB * 2 + 0]);
                acc[16 + qB * 2 + 1] = fmaf(xi2, fB1, acc[16 + qB * 2 + 1]);
                acc[24 + qB * 2 + 0] = fmaf(xi3, fB2, acc[24 + qB * 2 + 0]);
                acc[24 + qB * 2 + 1] = fmaf(xi3, fB3, acc[24 + qB * 2 + 1]);
            }
        }

        // -------- b2 term: even CTAs only (k-split partials must not double it) --------
        if (half == 0) {
#pragma unroll 8
            for (int i = 0; i < HID; i++) {
                float xi0 = s_x[er0 * X_STRIDE + i];
                float xi1 = s_x[er1 * X_STRIDE + i];
                float xi2 = s_x[er2 * X_STRIDE + i];
                float xi3 = s_x[er3 * X_STRIDE + i];
#pragma unroll
                for (int t4 = 0; t4 < 4; t4++) {
                    float2 bv = *(const float2*)(s_b2 + i * HID + t4 * 8 + ob);
                    acc[t4 * 2 + 0]      = fmaf(xi0, bv.x, acc[t4 * 2 + 0]);
                    acc[t4 * 2 + 1]      = fmaf(xi0, bv.y, acc[t4 * 2 + 1]);
                    acc[8 + t4 * 2 + 0]  = fmaf(xi1, bv.x, acc[8 + t4 * 2 + 0]);
                    acc[8 + t4 * 2 + 1]  = fmaf(xi1, bv.y, acc[8 + t4 * 2 + 1]);
                    acc[16 + t4 * 2 + 0] = fmaf(xi2, bv.x, acc[16 + t4 * 2 + 0]);
                    acc[16 + t4 * 2 + 1] = fmaf(xi2, bv.y, acc[16 + t4 * 2 + 1]);
                    acc[24 + t4 * 2 + 0] = fmaf(xi3, bv.x, acc[24 + t4 * 2 + 0]);
                    acc[24 + t4 * 2 + 1] = fmaf(xi3, bv.y, acc[24 + t4 * 2 + 1]);
                }
            }
        }

        // -------- scatter-add (partial over k; pairs of CTAs compose) --------
        {
            const int ers[4] = {er0, er1, er2, er3};
#pragma unroll
            for (int r = 0; r < 4; r++) {
                int ge = e0g + ers[r];
                if (ge < E) {
                    int dn = dst[ge];
                    float* op = out + (size_t)dn * HID;
#pragma unroll
                    for (int t4 = 0; t4 < 4; t4++) {
                        atomicAdd(op + t4 * 8 + ob + 0, acc[r * 8 + t4 * 2 + 0]);
                        atomicAdd(op + t4 * 8 + ob + 1, acc[r * 8 + t4 * 2 + 1]);
                    }
                }
            }
        }
        __syncwarp();   // lanes done with s_x before next tile overwrites
    }
}

extern "C" void kernel_launch(void* const* d_in, const int* in_sizes, int n_in,
                              void* d_out, int out_size) {
    const float* nf   = (const float*)d_in[0];
    const float* ef   = (const float*)d_in[1];
    const int*   src  = (const int*)d_in[2];
    const int*   dst  = (const int*)d_in[3];
    const float* W1   = (const float*)d_in[4];
    const float* b1   = (const float*)d_in[5];
    const float* W2   = (const float*)d_in[6];
    const float* b2   = (const float*)d_in[7];
    const float* bias = (const float*)d_in[8];
    float* out = (float*)d_out;

    const int E = in_sizes[2];
    const int ntiles = (E + TE - 1) / TE;

    int nsm = 0;
    cudaDeviceGetAttribute(&nsm, cudaDevAttrMultiProcessorCount, 0);
    if (nsm <= 0) nsm = 148;
    int grid = nsm & ~1;                       // even: CTA pairs split k
    if (grid > 2 * ntiles) grid = 2 * ntiles;
    if (grid < 2) grid = 2;

    cudaFuncSetAttribute(mpnn_mma_kernel,
                         cudaFuncAttributeMaxDynamicSharedMemorySize, SMEM_TOTAL);

    prep_b_kernel<<<64, 256>>>(W2);
    prep_w1_kernel<<<2, 256>>>(W1);
    init_out_kernel<<<(out_size + 255) / 256, 256>>>(out, bias, out_size);

    mpnn_mma_kernel<<<grid, NTH, SMEM_TOTAL>>>(nf, ef, src, dst, b1, b2, out, E, ntiles);
}

// round 15
// speedup vs baseline: 1.1055x; 1.1055x over previous
#include <cuda_runtime.h>
#include <cuda_fp16.h>
#include <cstdint>

#define HID   32
#define EDIM  16
#define EH    128
#define TE    256
#define NTH   256
#define X_STRIDE 33

// ---- smem offsets (bytes) ----
#define OFF_X    0              // 256 x 33 f32 = 33792
#define OFF_BB   33792          // 4 x 16384 = 65536
#define OFF_B2   99328          // 4096 -> 103424
#define OFF_W1H  103424         // 4096 (16 nt x 32 lane x uint2)
#define OFF_B1   111616         // 512
#define SMEM_TOTAL 112128       // 2 CTAs/SM

// W2 fp16 fragments: [nt(128)][kp(4)][lane(32)] = uint4{ks0.b01,ks0.b23 ; ks1.b01,ks1.b23}
__device__ uint4 g_Bfrag[128 * 4 * 32];
// W1 fp16 fragments (hi only): [nt(16)][lane(32)] = uint2
__device__ uint2 g_W1hi[16 * 32];

__device__ __forceinline__ uint32_t smem_u32(const void* p) {
    uint32_t a;
    asm("{ .reg .u64 t; cvta.to.shared.u64 t, %1; cvt.u32.u64 %0, t; }" : "=r"(a) : "l"(p));
    return a;
}
__device__ __forceinline__ uint32_t pkh(__half a, __half b) {
    __half2 v = __halves2half2(a, b);
    return *reinterpret_cast<uint32_t*>(&v);
}
__device__ __forceinline__ uint32_t rnd2h(float a, float b) {
    return pkh(__float2half_rn(a), __float2half_rn(b));
}
__device__ __forceinline__ void mma_f16(float& d0, float& d1, float& d2, float& d3,
                                        uint32_t a0, uint32_t a1, uint32_t a2, uint32_t a3,
                                        uint32_t b0, uint32_t b1) {
    asm volatile(
        "mma.sync.aligned.m16n8k16.row.col.f32.f16.f16.f32 "
        "{%0,%1,%2,%3}, {%4,%5,%6,%7}, {%8,%9}, {%0,%1,%2,%3};"
        : "+f"(d0), "+f"(d1), "+f"(d2), "+f"(d3)
        : "r"(a0), "r"(a1), "r"(a2), "r"(a3), "r"(b0), "r"(b1));
}

// ---------------- merged prep: init_out + W2 frags + W1 frags in ONE launch ----------------
__global__ void prep_all_kernel(const float* __restrict__ W2,
                                const float* __restrict__ W1,
                                float* __restrict__ out,
                                const float* __restrict__ bias,
                                int n_out, int nb_init) {
    int b = blockIdx.x;
    if (b < nb_init) {
        int i = b * 256 + threadIdx.x;
        if (i < n_out) out[i] = bias[i & (HID - 1)];
        return;
    }
    b -= nb_init;
    if (b < 64) {
        // W2 -> fragment-ordered fp16 (k-step pairs)
        int idx = b * 256 + threadIdx.x;
        int lane = idx & 31, kp = (idx >> 5) & 3, nt = idx >> 7;
        int g = lane >> 2, c = lane & 3;
        int n = nt * 8 + g;
        uint4 r;
        int k0 = (kp * 2) * 16 + 2 * c;
        r.x = rnd2h(W2[(size_t)k0 * 1024 + n], W2[(size_t)(k0 + 1) * 1024 + n]);
        r.y = rnd2h(W2[(size_t)(k0 + 8) * 1024 + n], W2[(size_t)(k0 + 9) * 1024 + n]);
        k0 = (kp * 2 + 1) * 16 + 2 * c;
        r.z = rnd2h(W2[(size_t)k0 * 1024 + n], W2[(size_t)(k0 + 1) * 1024 + n]);
        r.w = rnd2h(W2[(size_t)(k0 + 8) * 1024 + n], W2[(size_t)(k0 + 9) * 1024 + n]);
        g_Bfrag[idx] = r;
        return;
    }
    b -= 64;
    {
        // W1 -> fp16 fragments (hi only)
        int idx = b * 256 + threadIdx.x;
        if (idx >= 16 * 32) return;
        int lane = idx & 31, nt = idx >> 5;
        int g = lane >> 2, c = lane & 3;
        int n = nt * 8 + g;
        uint2 hi;
        hi.x = rnd2h(W1[(2 * c) * EH + n], W1[(2 * c + 1) * EH + n]);
        hi.y = rnd2h(W1[(2 * c + 8) * EH + n], W1[(2 * c + 9) * EH + n]);
        g_W1hi[idx] = hi;
    }
}

// ---------------- main fused kernel (R12 structure) ----------------
__global__ __launch_bounds__(NTH, 2)
void mpnn_mma_kernel(const float* __restrict__ nf,
                     const float* __restrict__ ef,
                     const int*   __restrict__ src,
                     const int*   __restrict__ dst,
                     const float* __restrict__ b1,
                     const float* __restrict__ b2,
                     float* __restrict__ out,
                     int E) {
    extern __shared__ __align__(1024) char sm[];
    const uint32_t sbase = smem_u32(sm);
    const int t = threadIdx.x;
    const int wid = t >> 5;
    const int lane = t & 31;
    const int e0g = blockIdx.x * TE;

    float* s_x   = (float*)(sm + OFF_X);
    float* s_b2  = (float*)(sm + OFF_B2);
    uint2* s_w1h = (uint2*)(sm + OFF_W1H);
    float* s_b1  = (float*)(sm + OFF_B1);

    // -------- phase 0: W1 frags, b1, x gather --------
    {
        for (int i = t; i < 16 * 32; i += NTH) s_w1h[i] = g_W1hi[i];
        if (t < EH / 4) ((float4*)s_b1)[t] = ((const float4*)b1)[t];
        const float4* nfg = (const float4*)nf;
        for (int j = t; j < TE * 8; j += NTH) {
            int e = j >> 3, c = j & 7, ge = e0g + e;
            float4 v = make_float4(0.f, 0.f, 0.f, 0.f);
            if (ge < E) { int sn = src[ge]; v = nfg[(size_t)sn * 8 + c]; }
            float* xr = s_x + e * X_STRIDE + c * 4;
            xr[0] = v.x; xr[1] = v.y; xr[2] = v.z; xr[3] = v.w;
        }
    }
    __syncthreads();

    // -------- issue B staging (chunks 0..2) + b2 early: overlaps phase A --------
    auto stage = [&](int chunk) {
        const uint4* srcp = g_Bfrag + chunk * 1024;
        uint32_t dstbase = sbase + OFF_BB + (chunk & 3) * 16384;
#pragma unroll
        for (int j = t; j < 1024; j += NTH) {
            uint32_t d = dstbase + j * 16;
            size_t gp = (size_t)__cvta_generic_to_global(srcp + j);
            asm volatile("cp.async.cg.shared.global [%0], [%1], 16;"
                         :: "r"(d), "l"(gp) : "memory");
        }
        asm volatile("cp.async.commit_group;" ::: "memory");
    };
    stage(0); stage(1); stage(2);

    for (int i = t; i < HID * HID / 4; i += NTH)
        ((float4*)s_b2)[i] = ((const float4*)b2)[i];

    // -------- phase A on tensor pipe (single fp16 pass): h = relu(ef@W1+b1) -> A frags --------
    const int g  = lane >> 2;
    const int c4 = lane & 3;
    const int eb = wid * 32;
    const int er0 = eb + g,      er1 = er0 + 8;   // m-tile 0 rows
    const int er2 = eb + 16 + g, er3 = er2 + 8;   // m-tile 1 rows

    uint32_t ehi[2][4];
    {
        const int rows[2][2] = {{er0, er1}, {er2, er3}};
#pragma unroll
        for (int mt = 0; mt < 2; mt++) {
#pragma unroll
            for (int rh = 0; rh < 2; rh++) {
                int ge = e0g + rows[mt][rh];
                float2 p0 = make_float2(0.f, 0.f), p1 = make_float2(0.f, 0.f);
                if (ge < E) {
                    p0 = *(const float2*)(ef + (size_t)ge * EDIM + 2 * c4);
                    p1 = *(const float2*)(ef + (size_t)ge * EDIM + 2 * c4 + 8);
                }
                ehi[mt][rh]     = rnd2h(p0.x, p0.y);   // a0/a1
                ehi[mt][2 + rh] = rnd2h(p1.x, p1.y);   // a2/a3
            }
        }
    }

    uint32_t a0[8][4], a1[8][4];
#pragma unroll
    for (int ks = 0; ks < 8; ks++) {
        uint2 whA = s_w1h[(2 * ks) * 32 + lane];
        uint2 whB = s_w1h[(2 * ks + 1) * 32 + lane];
        float2 b1A = *(const float2*)(s_b1 + ks * 16 + 2 * c4);
        float2 b1B = *(const float2*)(s_b1 + ks * 16 + 8 + 2 * c4);
#pragma unroll
        for (int mt = 0; mt < 2; mt++) {
            float d0 = 0.f, d1 = 0.f, d2 = 0.f, d3 = 0.f;   // n-tile 2ks
            float f0 = 0.f, f1 = 0.f, f2 = 0.f, f3 = 0.f;   // n-tile 2ks+1
            mma_f16(d0, d1, d2, d3, ehi[mt][0], ehi[mt][1], ehi[mt][2], ehi[mt][3], whA.x, whA.y);
            mma_f16(f0, f1, f2, f3, ehi[mt][0], ehi[mt][1], ehi[mt][2], ehi[mt][3], whB.x, whB.y);
            uint32_t* A = mt ? a1[ks] : a0[ks];
            A[0] = rnd2h(fmaxf(d0 + b1A.x, 0.f), fmaxf(d1 + b1A.y, 0.f));
            A[1] = rnd2h(fmaxf(d2 + b1A.x, 0.f), fmaxf(d3 + b1A.y, 0.f));
            A[2] = rnd2h(fmaxf(f0 + b1B.x, 0.f), fmaxf(f1 + b1B.y, 0.f));
            A[3] = rnd2h(fmaxf(f2 + b1B.x, 0.f), fmaxf(f3 + b1B.y, 0.f));
        }
    }

    float acc[32];
#pragma unroll
    for (int i = 0; i < 32; i++) acc[i] = 0.f;

    asm volatile("cp.async.wait_group 2;" ::: "memory");
    __syncthreads();   // buffer 0 ready everywhere; x/b2 visible

    // -------- mainloop: 16 chunks, 4-buffer ring, one barrier per chunk --------
    for (int ch = 0; ch < 16; ch++) {
        const uint4* bb = (const uint4*)(sm + OFF_BB + (ch & 3) * 16384);
#pragma unroll
        for (int ig = 0; ig < 2; ig++) {
            int i = ch * 2 + ig;
            float xi0 = s_x[er0 * X_STRIDE + i];
            float xi1 = s_x[er1 * X_STRIDE + i];
            float xi2 = s_x[er2 * X_STRIDE + i];
            float xi3 = s_x[er3 * X_STRIDE + i];
#pragma unroll
            for (int q = 0; q < 4; q++) {
                int ntl = ig * 4 + q;
                float d0 = 0.f, d1 = 0.f, d2 = 0.f, d3 = 0.f;
                float f0 = 0.f, f1 = 0.f, f2 = 0.f, f3 = 0.f;
                const uint4* bp = bb + ntl * 128 + lane;
#pragma unroll
                for (int kp = 0; kp < 4; kp++) {
                    uint4 b = bp[kp * 32];
                    int k0 = kp * 2;
                    mma_f16(d0, d1, d2, d3, a0[k0][0], a0[k0][1], a0[k0][2], a0[k0][3], b.x, b.y);
                    mma_f16(f0, f1, f2, f3, a1[k0][0], a1[k0][1], a1[k0][2], a1[k0][3], b.x, b.y);
                    mma_f16(d0, d1, d2, d3, a0[k0 + 1][0], a0[k0 + 1][1], a0[k0 + 1][2], a0[k0 + 1][3], b.z, b.w);
                    mma_f16(f0, f1, f2, f3, a1[k0 + 1][0], a1[k0 + 1][1], a1[k0 + 1][2], a1[k0 + 1][3], b.z, b.w);
                }
                acc[q * 2 + 0]      = fmaf(xi0, d0, acc[q * 2 + 0]);
                acc[q * 2 + 1]      = fmaf(xi0, d1, acc[q * 2 + 1]);
                acc[8 + q * 2 + 0]  = fmaf(xi1, d2, acc[8 + q * 2 + 0]);
                acc[8 + q * 2 + 1]  = fmaf(xi1, d3, acc[8 + q * 2 + 1]);
                acc[16 + q * 2 + 0] = fmaf(xi2, f0, acc[16 + q * 2 + 0]);
                acc[16 + q * 2 + 1] = fmaf(xi2, f1, acc[16 + q * 2 + 1]);
                acc[24 + q * 2 + 0] = fmaf(xi3, f2, acc[24 + q * 2 + 0]);
                acc[24 + q * 2 + 1] = fmaf(xi3, f3, acc[24 + q * 2 + 1]);
            }
        }
        if (ch + 3 < 16) stage(ch + 3);
        if (ch < 15) {
            asm volatile("cp.async.wait_group 2;" ::: "memory");
            __syncthreads();
        }
    }

    // -------- b2 term: msg[e,o] += sum_i x[e,i] * b2[i*32+o] --------
    const int ob = 2 * c4;
#pragma unroll 8
    for (int i = 0; i < HID; i++) {
        float xi0 = s_x[er0 * X_STRIDE + i];
        float xi1 = s_x[er1 * X_STRIDE + i];
        float xi2 = s_x[er2 * X_STRIDE + i];
        float xi3 = s_x[er3 * X_STRIDE + i];
#pragma unroll
        for (int t4 = 0; t4 < 4; t4++) {
            float2 bv = *(const float2*)(s_b2 + i * HID + t4 * 8 + ob);
            acc[t4 * 2 + 0]      = fmaf(xi0, bv.x, acc[t4 * 2 + 0]);
            acc[t4 * 2 + 1]      = fmaf(xi0, bv.y, acc[t4 * 2 + 1]);
            acc[8 + t4 * 2 + 0]  = fmaf(xi1, bv.x, acc[8 + t4 * 2 + 0]);
            acc[8 + t4 * 2 + 1]  = fmaf(xi1, bv.y, acc[8 + t4 * 2 + 1]);
            acc[16 + t4 * 2 + 0] = fmaf(xi2, bv.x, acc[16 + t4 * 2 + 0]);
            acc[16 + t4 * 2 + 1] = fmaf(xi2, bv.y, acc[16 + t4 * 2 + 1]);
            acc[24 + t4 * 2 + 0] = fmaf(xi3, bv.x, acc[24 + t4 * 2 + 0]);
            acc[24 + t4 * 2 + 1] = fmaf(xi3, bv.y, acc[24 + t4 * 2 + 1]);
        }
    }

    // -------- scatter-add --------
    {
        const int ers[4] = {er0, er1, er2, er3};
#pragma unroll
        for (int r = 0; r < 4; r++) {
            int ge = e0g + ers[r];
            if (ge < E) {
                int dn = dst[ge];
                float* op = out + (size_t)dn * HID;
#pragma unroll
                for (int t4 = 0; t4 < 4; t4++) {
                    atomicAdd(op + t4 * 8 + ob + 0, acc[r * 8 + t4 * 2 + 0]);
                    atomicAdd(op + t4 * 8 + ob + 1, acc[r * 8 + t4 * 2 + 1]);
                }
            }
        }
    }
}

extern "C" void kernel_launch(void* const* d_in, const int* in_sizes, int n_in,
                              void* d_out, int out_size) {
    const float* nf   = (const float*)d_in[0];
    const float* ef   = (const float*)d_in[1];
    const int*   src  = (const int*)d_in[2];
    const int*   dst  = (const int*)d_in[3];
    const float* W1   = (const float*)d_in[4];
    const float* b1   = (const float*)d_in[5];
    const float* W2   = (const float*)d_in[6];
    const float* b2   = (const float*)d_in[7];
    const float* bias = (const float*)d_in[8];
    float* out = (float*)d_out;

    const int E = in_sizes[2];

    cudaFuncSetAttribute(mpnn_mma_kernel,
                         cudaFuncAttributeMaxDynamicSharedMemorySize, SMEM_TOTAL);

    int nb_init = (out_size + 255) / 256;
    prep_all_kernel<<<nb_init + 64 + 2, 256>>>(W2, W1, out, bias, out_size, nb_init);

    int grid = (E + TE - 1) / TE;
    mpnn_mma_kernel<<<grid, NTH, SMEM_TOTAL>>>(nf, ef, src, dst, b1, b2, out, E);
}

// round 17
// speedup vs baseline: 1.1073x; 1.0017x over previous
#include <cuda_runtime.h>
#include <cuda_fp16.h>
#include <cstdint>

#define HID   32
#define EDIM  16
#define EH    128
#define TE    256
#define NTH   256
#define X_STRIDE 33

// ---- smem offsets (bytes) ----
#define OFF_X    0              // 256 x 33 f32 = 33792
#define OFF_BB   33792          // 4 x 16384 = 65536
#define OFF_B2   99328          // 4096 -> 103424
#define OFF_W1H  103424         // 4096 (16 nt x 32 lane x uint2)
#define OFF_B1   111616         // 512
#define SMEM_TOTAL 112128       // 2 CTAs/SM

// W2 fp16 fragments: [nt(128)][kp(4)][lane(32)] = uint4{ks0.b01,ks0.b23 ; ks1.b01,ks1.b23}
__device__ uint4 g_Bfrag[128 * 4 * 32];
// W1 fp16 fragments (hi only): [nt(16)][lane(32)] = uint2
__device__ uint2 g_W1hi[16 * 32];

__device__ __forceinline__ uint32_t smem_u32(const void* p) {
    uint32_t a;
    asm("{ .reg .u64 t; cvta.to.shared.u64 t, %1; cvt.u32.u64 %0, t; }" : "=r"(a) : "l"(p));
    return a;
}
__device__ __forceinline__ uint32_t pkh(__half a, __half b) {
    __half2 v = __halves2half2(a, b);
    return *reinterpret_cast<uint32_t*>(&v);
}
__device__ __forceinline__ uint32_t rnd2h(float a, float b) {
    return pkh(__float2half_rn(a), __float2half_rn(b));
}
__device__ __forceinline__ void mma_f16(float& d0, float& d1, float& d2, float& d3,
                                        uint32_t a0, uint32_t a1, uint32_t a2, uint32_t a3,
                                        uint32_t b0, uint32_t b1) {
    asm volatile(
        "mma.sync.aligned.m16n8k16.row.col.f32.f16.f16.f32 "
        "{%0,%1,%2,%3}, {%4,%5,%6,%7}, {%8,%9}, {%0,%1,%2,%3};"
        : "+f"(d0), "+f"(d1), "+f"(d2), "+f"(d3)
        : "r"(a0), "r"(a1), "r"(a2), "r"(a3), "r"(b0), "r"(b1));
}
// vector reduction: RED.E.ADD.F32x2 (no return) — sm_90+
__device__ __forceinline__ void red_add_f32x2(float* p, float a, float b) {
    asm volatile("red.global.add.v2.f32 [%0], {%1, %2};"
                 :: "l"(p), "f"(a), "f"(b) : "memory");
}

// ---------------- merged prep: init_out + W2 frags + W1 frags in ONE launch ----------------
__global__ void prep_all_kernel(const float* __restrict__ W2,
                                const float* __restrict__ W1,
                                float* __restrict__ out,
                                const float* __restrict__ bias,
                                int n_out, int nb_init) {
    int b = blockIdx.x;
    if (b < nb_init) {
        int i = b * 256 + threadIdx.x;
        if (i < n_out) out[i] = bias[i & (HID - 1)];
        return;
    }
    b -= nb_init;
    if (b < 64) {
        // W2 -> fragment-ordered fp16 (k-step pairs)
        int idx = b * 256 + threadIdx.x;
        int lane = idx & 31, kp = (idx >> 5) & 3, nt = idx >> 7;
        int g = lane >> 2, c = lane & 3;
        int n = nt * 8 + g;
        uint4 r;
        int k0 = (kp * 2) * 16 + 2 * c;
        r.x = rnd2h(W2[(size_t)k0 * 1024 + n], W2[(size_t)(k0 + 1) * 1024 + n]);
        r.y = rnd2h(W2[(size_t)(k0 + 8) * 1024 + n], W2[(size_t)(k0 + 9) * 1024 + n]);
        k0 = (kp * 2 + 1) * 16 + 2 * c;
        r.z = rnd2h(W2[(size_t)k0 * 1024 + n], W2[(size_t)(k0 + 1) * 1024 + n]);
        r.w = rnd2h(W2[(size_t)(k0 + 8) * 1024 + n], W2[(size_t)(k0 + 9) * 1024 + n]);
        g_Bfrag[idx] = r;
        return;
    }
    b -= 64;
    {
        // W1 -> fp16 fragments (hi only)
        int idx = b * 256 + threadIdx.x;
        if (idx >= 16 * 32) return;
        int lane = idx & 31, nt = idx >> 5;
        int g = lane >> 2, c = lane & 3;
        int n = nt * 8 + g;
        uint2 hi;
        hi.x = rnd2h(W1[(2 * c) * EH + n], W1[(2 * c + 1) * EH + n]);
        hi.y = rnd2h(W1[(2 * c + 8) * EH + n], W1[(2 * c + 9) * EH + n]);
        g_W1hi[idx] = hi;
    }
}

// ---------------- main fused kernel ----------------
__global__ __launch_bounds__(NTH, 2)
void mpnn_mma_kernel(const float* __restrict__ nf,
                     const float* __restrict__ ef,
                     const int*   __restrict__ src,
                     const int*   __restrict__ dst,
                     const float* __restrict__ b1,
                     const float* __restrict__ b2,
                     float* __restrict__ out,
                     int E) {
    extern __shared__ __align__(1024) char sm[];
    const uint32_t sbase = smem_u32(sm);
    const int t = threadIdx.x;
    const int wid = t >> 5;
    const int lane = t & 31;
    const int e0g = blockIdx.x * TE;

    float* s_x   = (float*)(sm + OFF_X);
    float* s_b2  = (float*)(sm + OFF_B2);
    uint2* s_w1h = (uint2*)(sm + OFF_W1H);
    float* s_b1  = (float*)(sm + OFF_B1);

    // -------- stage B chunks 0..2 FIRST: L2 latency hides under the gather --------
    auto stage = [&](int chunk) {
        const uint4* srcp = g_Bfrag + chunk * 1024;
        uint32_t dstbase = sbase + OFF_BB + (chunk & 3) * 16384;
#pragma unroll
        for (int j = t; j < 1024; j += NTH) {
            uint32_t d = dstbase + j * 16;
            size_t gp = (size_t)__cvta_generic_to_global(srcp + j);
            asm volatile("cp.async.cg.shared.global [%0], [%1], 16;"
                         :: "r"(d), "l"(gp) : "memory");
        }
        asm volatile("cp.async.commit_group;" ::: "memory");
    };
    stage(0); stage(1); stage(2);

    const int g  = lane >> 2;
    const int c4 = lane & 3;
    const int eb = wid * 32;
    const int er0 = eb + g,      er1 = er0 + 8;   // m-tile 0 rows
    const int er2 = eb + 16 + g, er3 = er2 + 8;   // m-tile 1 rows

    // -------- prefetch dst indices for this warp's 4 edges (hide LDG latency) --------
    int dn[4];
    {
        const int ers[4] = {er0, er1, er2, er3};
#pragma unroll
        for (int r = 0; r < 4; r++) {
            int ge = e0g + ers[r];
            dn[r] = (ge < E) ? dst[ge] : -1;
        }
    }

    // -------- phase 0: W1 frags, b1, b2, x gather --------
    {
        for (int i = t; i < 16 * 32; i += NTH) s_w1h[i] = g_W1hi[i];
        if (t < EH / 4) ((float4*)s_b1)[t] = ((const float4*)b1)[t];
        for (int i = t; i < HID * HID / 4; i += NTH)
            ((float4*)s_b2)[i] = ((const float4*)b2)[i];
        const float4* nfg = (const float4*)nf;
        for (int j = t; j < TE * 8; j += NTH) {
            int e = j >> 3, c = j & 7, ge = e0g + e;
            float4 v = make_float4(0.f, 0.f, 0.f, 0.f);
            if (ge < E) { int sn = src[ge]; v = nfg[(size_t)sn * 8 + c]; }
            float* xr = s_x + e * X_STRIDE + c * 4;
            xr[0] = v.x; xr[1] = v.y; xr[2] = v.z; xr[3] = v.w;
        }
    }
    __syncthreads();

    // -------- phase A on tensor pipe (single fp16 pass): h = relu(ef@W1+b1) -> A frags --------
    uint32_t ehi[2][4];
    {
        const int rows[2][2] = {{er0, er1}, {er2, er3}};
#pragma unroll
        for (int mt = 0; mt < 2; mt++) {
#pragma unroll
            for (int rh = 0; rh < 2; rh++) {
                int ge = e0g + rows[mt][rh];
                float2 p0 = make_float2(0.f, 0.f), p1 = make_float2(0.f, 0.f);
                if (ge < E) {
                    p0 = *(const float2*)(ef + (size_t)ge * EDIM + 2 * c4);
                    p1 = *(const float2*)(ef + (size_t)ge * EDIM + 2 * c4 + 8);
                }
                ehi[mt][rh]     = rnd2h(p0.x, p0.y);   // a0/a1
                ehi[mt][2 + rh] = rnd2h(p1.x, p1.y);   // a2/a3
            }
        }
    }

    uint32_t a0[8][4], a1[8][4];
#pragma unroll
    for (int ks = 0; ks < 8; ks++) {
        uint2 whA = s_w1h[(2 * ks) * 32 + lane];
        uint2 whB = s_w1h[(2 * ks + 1) * 32 + lane];
        float2 b1A = *(const float2*)(s_b1 + ks * 16 + 2 * c4);
        float2 b1B = *(const float2*)(s_b1 + ks * 16 + 8 + 2 * c4);
#pragma unroll
        for (int mt = 0; mt < 2; mt++) {
            float d0 = 0.f, d1 = 0.f, d2 = 0.f, d3 = 0.f;   // n-tile 2ks
            float f0 = 0.f, f1 = 0.f, f2 = 0.f, f3 = 0.f;   // n-tile 2ks+1
            mma_f16(d0, d1, d2, d3, ehi[mt][0], ehi[mt][1], ehi[mt][2], ehi[mt][3], whA.x, whA.y);
            mma_f16(f0, f1, f2, f3, ehi[mt][0], ehi[mt][1], ehi[mt][2], ehi[mt][3], whB.x, whB.y);
            uint32_t* A = mt ? a1[ks] : a0[ks];
            A[0] = rnd2h(fmaxf(d0 + b1A.x, 0.f), fmaxf(d1 + b1A.y, 0.f));
            A[1] = rnd2h(fmaxf(d2 + b1A.x, 0.f), fmaxf(d3 + b1A.y, 0.f));
            A[2] = rnd2h(fmaxf(f0 + b1B.x, 0.f), fmaxf(f1 + b1B.y, 0.f));
            A[3] = rnd2h(fmaxf(f2 + b1B.x, 0.f), fmaxf(f3 + b1B.y, 0.f));
        }
    }

    float acc[32];
#pragma unroll
    for (int i = 0; i < 32; i++) acc[i] = 0.f;

    asm volatile("cp.async.wait_group 2;" ::: "memory");
    __syncthreads();   // buffer 0 ready everywhere; x/b2 visible

    // -------- mainloop: 16 chunks, 4-buffer ring, one barrier per chunk --------
    for (int ch = 0; ch < 16; ch++) {
        const uint4* bb = (const uint4*)(sm + OFF_BB + (ch & 3) * 16384);
#pragma unroll
        for (int ig = 0; ig < 2; ig++) {
            int i = ch * 2 + ig;
            float xi0 = s_x[er0 * X_STRIDE + i];
            float xi1 = s_x[er1 * X_STRIDE + i];
            float xi2 = s_x[er2 * X_STRIDE + i];
            float xi3 = s_x[er3 * X_STRIDE + i];
#pragma unroll
            for (int q = 0; q < 4; q++) {
                int ntl = ig * 4 + q;
                float d0 = 0.f, d1 = 0.f, d2 = 0.f, d3 = 0.f;
                float f0 = 0.f, f1 = 0.f, f2 = 0.f, f3 = 0.f;
                const uint4* bp = bb + ntl * 128 + lane;
#pragma unroll
                for (int kp = 0; kp < 4; kp++) {
                    uint4 b = bp[kp * 32];
                    int k0 = kp * 2;
                    mma_f16(d0, d1, d2, d3, a0[k0][0], a0[k0][1], a0[k0][2], a0[k0][3], b.x, b.y);
                    mma_f16(f0, f1, f2, f3, a1[k0][0], a1[k0][1], a1[k0][2], a1[k0][3], b.x, b.y);
                    mma_f16(d0, d1, d2, d3, a0[k0 + 1][0], a0[k0 + 1][1], a0[k0 + 1][2], a0[k0 + 1][3], b.z, b.w);
                    mma_f16(f0, f1, f2, f3, a1[k0 + 1][0], a1[k0 + 1][1], a1[k0 + 1][2], a1[k0 + 1][3], b.z, b.w);
                }
                acc[q * 2 + 0]      = fmaf(xi0, d0, acc[q * 2 + 0]);
                acc[q * 2 + 1]      = fmaf(xi0, d1, acc[q * 2 + 1]);
                acc[8 + q * 2 + 0]  = fmaf(xi1, d2, acc[8 + q * 2 + 0]);
                acc[8 + q * 2 + 1]  = fmaf(xi1, d3, acc[8 + q * 2 + 1]);
                acc[16 + q * 2 + 0] = fmaf(xi2, f0, acc[16 + q * 2 + 0]);
                acc[16 + q * 2 + 1] = fmaf(xi2, f1, acc[16 + q * 2 + 1]);
                acc[24 + q * 2 + 0] = fmaf(xi3, f2, acc[24 + q * 2 + 0]);
                acc[24 + q * 2 + 1] = fmaf(xi3, f3, acc[24 + q * 2 + 1]);
            }
        }
        if (ch + 3 < 16) stage(ch + 3);
        if (ch < 15) {
            asm volatile("cp.async.wait_group 2;" ::: "memory");
            __syncthreads();
        }
    }

    // -------- b2 term: msg[e,o] += sum_i x[e,i] * b2[i*32+o] --------
    const int ob = 2 * c4;
#pragma unroll 8
    for (int i = 0; i < HID; i++) {
        float xi0 = s_x[er0 * X_STRIDE + i];
        float xi1 = s_x[er1 * X_STRIDE + i];
        float xi2 = s_x[er2 * X_STRIDE + i];
        float xi3 = s_x[er3 * X_STRIDE + i];
#pragma unroll
        for (int t4 = 0; t4 < 4; t4++) {
            float2 bv = *(const float2*)(s_b2 + i * HID + t4 * 8 + ob);
            acc[t4 * 2 + 0]      = fmaf(xi0, bv.x, acc[t4 * 2 + 0]);
            acc[t4 * 2 + 1]      = fmaf(xi0, bv.y, acc[t4 * 2 + 1]);
            acc[8 + t4 * 2 + 0]  = fmaf(xi1, bv.x, acc[8 + t4 * 2 + 0]);
            acc[8 + t4 * 2 + 1]  = fmaf(xi1, bv.y, acc[8 + t4 * 2 + 1]);
            acc[16 + t4 * 2 + 0] = fmaf(xi2, bv.x, acc[16 + t4 * 2 + 0]);
            acc[16 + t4 * 2 + 1] = fmaf(xi2, bv.y, acc[16 + t4 * 2 + 1]);
            acc[24 + t4 * 2 + 0] = fmaf(xi3, bv.x, acc[24 + t4 * 2 + 0]);
            acc[24 + t4 * 2 + 1] = fmaf(xi3, bv.y, acc[24 + t4 * 2 + 1]);
        }
    }

    // -------- scatter-add: vector RED.F32x2, prefetched dst --------
#pragma unroll
    for (int r = 0; r < 4; r++) {
        if (dn[r] >= 0) {
            float* op = out + (size_t)dn[r] * HID + ob;
#pragma unroll
            for (int t4 = 0; t4 < 4; t4++)
                red_add_f32x2(op + t4 * 8, acc[r * 8 + t4 * 2 + 0], acc[r * 8 + t4 * 2 + 1]);
        }
    }
}

extern "C" void kernel_launch(void* const* d_in, const int* in_sizes, int n_in,
                              void* d_out, int out_size) {
    const float* nf   = (const float*)d_in[0];
    const float* ef   = (const float*)d_in[1];
    const int*   src  = (const int*)d_in[2];
    const int*   dst  = (const int*)d_in[3];
    const float* W1   = (const float*)d_in[4];
    const float* b1   = (const float*)d_in[5];
    const float* W2   = (const float*)d_in[6];
    const float* b2   = (const float*)d_in[7];
    const float* bias = (const float*)d_in[8];
    float* out = (float*)d_out;

    const int E = in_sizes[2];

    cudaFuncSetAttribute(mpnn_mma_kernel,
                         cudaFuncAttributeMaxDynamicSharedMemorySize, SMEM_TOTAL);

    int nb_init = (out_size + 255) / 256;
    prep_all_kernel<<<nb_init + 64 + 2, 256>>>(W2, W1, out, bias, out_size, nb_init);

    int grid = (E + TE - 1) / TE;
    mpnn_mma_kernel<<<grid, NTH, SMEM_TOTAL>>>(nf, ef, src, dst, b1, b2, out, E);
}